// round 1
// baseline (speedup 1.0000x reference)
#include <cuda_runtime.h>

// Problem constants
#define B_   2
#define S_   2048
#define D_   2048
#define H_   16
#define HD_  128
#define R_   32
#define M_TOK (B_ * S_)              // 4096 tokens
#define LORA_SCALE (1.0f / 32.0f)

// ---------------------------------------------------------------------------
// Scratch (allocation-free rule: __device__ globals)
// ---------------------------------------------------------------------------
static __device__ float g_qkv[M_TOK * 3 * D_];   // [4096, 6144]  96 MB
static __device__ float g_attn[M_TOK * D_];      // [4096, 2048]  32 MB
static __device__ float g_t1[M_TOK * R_];
static __device__ float g_t2[M_TOK * R_];

// ---------------------------------------------------------------------------
// Small LoRA-down GEMM: T[M,32] = X[M,K] @ A[K,32]
// Block: 256 threads -> 32 rows x 32 cols per block.
// ---------------------------------------------------------------------------
__global__ void __launch_bounds__(256) lora_down_kernel(
    const float* __restrict__ X, const float* __restrict__ Amat,
    float* __restrict__ Tout, int M, int K)
{
    __shared__ __align__(16) float Xs[32][68];   // pad 68: float4-aligned rows
    __shared__ __align__(16) float As2[64][36];

    const int tid = threadIdx.x;
    const int m0  = blockIdx.x * 32;
    const int n   = tid & 31;
    const int mq  = (tid >> 5) * 4;

    float acc[4] = {0.f, 0.f, 0.f, 0.f};

    for (int k0 = 0; k0 < K; k0 += 64) {
        __syncthreads();
        // X tile: 32 x 64 -> 512 float4, 2 per thread
        #pragma unroll
        for (int l = 0; l < 2; l++) {
            int idx = tid + l * 256;
            int m   = idx >> 4;           // 0..31
            int k4  = (idx & 15) << 2;    // 0..60
            *(float4*)&Xs[m][k4] =
                *(const float4*)&X[(size_t)(m0 + m) * K + k0 + k4];
        }
        // A tile: 64 x 32 -> 512 float4
        #pragma unroll
        for (int l = 0; l < 2; l++) {
            int idx = tid + l * 256;
            int kk  = idx >> 3;           // 0..63
            int n4  = (idx & 7) << 2;     // 0..28
            *(float4*)&As2[kk][n4] =
                *(const float4*)&Amat[(size_t)(k0 + kk) * 32 + n4];
        }
        __syncthreads();
        #pragma unroll 16
        for (int kk = 0; kk < 64; kk++) {
            float a = As2[kk][n];
            acc[0] = fmaf(Xs[mq + 0][kk], a, acc[0]);
            acc[1] = fmaf(Xs[mq + 1][kk], a, acc[1]);
            acc[2] = fmaf(Xs[mq + 2][kk], a, acc[2]);
            acc[3] = fmaf(Xs[mq + 3][kk], a, acc[3]);
        }
    }
    #pragma unroll
    for (int i = 0; i < 4; i++)
        Tout[(size_t)(m0 + mq + i) * 32 + n] = acc[i];
}

// ---------------------------------------------------------------------------
// Fused SGEMM:  C[M,N] = A[M,K] @ W[N,K]^T  +  T[M,32] @ Bq[32,N] * lscale
// Tile 128x128x16, 256 threads, 8x8 micro-tile (two 4x4 quads at +0 / +64).
// LoRA handled as 32 extra K-steps with alternate loaders.
// ---------------------------------------------------------------------------
#define GBM 128
#define GBN 128
#define GBK 16

__global__ void __launch_bounds__(256, 2) sgemm_nt_lora(
    const float* __restrict__ A, const float* __restrict__ W,
    const float* __restrict__ T, const float* __restrict__ Bq,
    float* __restrict__ C, int M, int N, int K, float lscale)
{
    __shared__ __align__(16) float As[GBK][GBM + 4];
    __shared__ __align__(16) float Bs[GBK][GBN + 4];

    const int tid = threadIdx.x;
    const int tx  = tid & 15;
    const int ty  = tid >> 4;
    const int m0  = blockIdx.y * GBM;
    const int n0  = blockIdx.x * GBN;

    float acc[8][8];
    #pragma unroll
    for (int i = 0; i < 8; i++)
        #pragma unroll
        for (int j = 0; j < 8; j++) acc[i][j] = 0.f;

    // --- main K loop ---
    for (int k0 = 0; k0 < K; k0 += GBK) {
        __syncthreads();
        #pragma unroll
        for (int l = 0; l < 2; l++) {
            int idx = tid + l * 256;
            int row = idx >> 2;            // 0..127
            int kc  = (idx & 3) << 2;      // 0,4,8,12
            float4 v = *(const float4*)&A[(size_t)(m0 + row) * K + k0 + kc];
            As[kc + 0][row] = v.x; As[kc + 1][row] = v.y;
            As[kc + 2][row] = v.z; As[kc + 3][row] = v.w;
        }
        #pragma unroll
        for (int l = 0; l < 2; l++) {
            int idx = tid + l * 256;
            int row = idx >> 2;
            int kc  = (idx & 3) << 2;
            float4 v = *(const float4*)&W[(size_t)(n0 + row) * K + k0 + kc];
            Bs[kc + 0][row] = v.x; Bs[kc + 1][row] = v.y;
            Bs[kc + 2][row] = v.z; Bs[kc + 3][row] = v.w;
        }
        __syncthreads();
        #pragma unroll
        for (int kk = 0; kk < GBK; kk++) {
            float a[8], b[8];
            *(float4*)&a[0] = *(const float4*)&As[kk][ty * 4];
            *(float4*)&a[4] = *(const float4*)&As[kk][64 + ty * 4];
            *(float4*)&b[0] = *(const float4*)&Bs[kk][tx * 4];
            *(float4*)&b[4] = *(const float4*)&Bs[kk][64 + tx * 4];
            #pragma unroll
            for (int i = 0; i < 8; i++)
                #pragma unroll
                for (int j = 0; j < 8; j++)
                    acc[i][j] = fmaf(a[i], b[j], acc[i][j]);
        }
    }

    // --- LoRA tail: 32 extra K-steps: A <- T[M,32], B <- Bq[32,N]*lscale ---
    if (T != nullptr) {
        for (int r0 = 0; r0 < 32; r0 += GBK) {
            __syncthreads();
            #pragma unroll
            for (int l = 0; l < 2; l++) {
                int idx = tid + l * 256;
                int row = idx >> 2;
                int kc  = (idx & 3) << 2;
                float4 v = *(const float4*)&T[(size_t)(m0 + row) * 32 + r0 + kc];
                As[kc + 0][row] = v.x; As[kc + 1][row] = v.y;
                As[kc + 2][row] = v.z; As[kc + 3][row] = v.w;
            }
            #pragma unroll
            for (int l = 0; l < 2; l++) {
                int idx = tid + l * 256;
                int kk  = idx >> 5;            // 0..15
                int n4  = (idx & 31) << 2;     // 0..124
                float4 v = *(const float4*)&Bq[(size_t)(r0 + kk) * N + n0 + n4];
                v.x *= lscale; v.y *= lscale; v.z *= lscale; v.w *= lscale;
                *(float4*)&Bs[kk][n4] = v;
            }
            __syncthreads();
            #pragma unroll
            for (int kk = 0; kk < GBK; kk++) {
                float a[8], b[8];
                *(float4*)&a[0] = *(const float4*)&As[kk][ty * 4];
                *(float4*)&a[4] = *(const float4*)&As[kk][64 + ty * 4];
                *(float4*)&b[0] = *(const float4*)&Bs[kk][tx * 4];
                *(float4*)&b[4] = *(const float4*)&Bs[kk][64 + tx * 4];
                #pragma unroll
                for (int i = 0; i < 8; i++)
                    #pragma unroll
                    for (int j = 0; j < 8; j++)
                        acc[i][j] = fmaf(a[i], b[j], acc[i][j]);
            }
        }
    }

    // --- write back ---
    #pragma unroll
    for (int ih = 0; ih < 2; ih++)
        #pragma unroll
        for (int ii = 0; ii < 4; ii++) {
            int row = m0 + ih * 64 + ty * 4 + ii;
            #pragma unroll
            for (int jh = 0; jh < 2; jh++) {
                float4 v;
                v.x = acc[ih * 4 + ii][jh * 4 + 0];
                v.y = acc[ih * 4 + ii][jh * 4 + 1];
                v.z = acc[ih * 4 + ii][jh * 4 + 2];
                v.w = acc[ih * 4 + ii][jh * 4 + 3];
                *(float4*)&C[(size_t)row * N + n0 + jh * 64 + tx * 4] = v;
            }
        }
}

// ---------------------------------------------------------------------------
// Flash attention (fp32, online softmax).
// Grid: (S/64, H, B). Block: 256 threads. Per block: 64 q-rows, full head.
// smem (dynamic): Qs[64][132], KVs[64][132] (K then reused for V), Ps[64][68]
// Thread map: tx = tid&15, ty = tid>>4; scores (ty+16i, tx+16j);
//             O cols d = tx*4 + 64*jj (two float4 per row).
// ---------------------------------------------------------------------------
#define QPAD 132
#define PPAD 68
#define ATTN_SMEM_BYTES ((2 * 64 * QPAD + 64 * PPAD) * 4)

__global__ void __launch_bounds__(256, 2) attn_kernel(
    const float* __restrict__ qkv, const float* __restrict__ alibi,
    const float* __restrict__ pad, float* __restrict__ out)
{
    extern __shared__ __align__(16) float sm[];
    float* Qs  = sm;                      // 64 * 132
    float* KVs = sm + 64 * QPAD;          // 64 * 132
    float* Ps  = sm + 2 * 64 * QPAD;      // 64 * 68

    const int q0 = blockIdx.x * 64;
    const int h  = blockIdx.y;
    const int b  = blockIdx.z;
    const int tid = threadIdx.x;
    const int tx = tid & 15;
    const int ty = tid >> 4;

    const int ROWSTRIDE = 3 * D_;   // qkv token stride (6144 floats)

    // load Q tile [64 x 128]
    {
        const float* qbase = qkv + (size_t)(b * S_ + q0) * ROWSTRIDE + h * HD_;
        #pragma unroll
        for (int l = 0; l < 8; l++) {
            int idx = tid + l * 256;
            int m   = idx >> 5;            // 0..63
            int d4  = (idx & 31) << 2;     // 0..124
            *(float4*)&Qs[m * QPAD + d4] =
                *(const float4*)&qbase[(size_t)m * ROWSTRIDE + d4];
        }
    }

    float m_cur[4], l_cur[4], o[4][8];
    #pragma unroll
    for (int i = 0; i < 4; i++) {
        m_cur[i] = -1e30f; l_cur[i] = 0.f;
        #pragma unroll
        for (int jj = 0; jj < 8; jj++) o[i][jj] = 0.f;
    }

    const float sscale = 0.08838834764831845f;   // 1/sqrt(128)

    for (int kt = 0; kt < S_ / 64; kt++) {
        const int k0 = kt * 64;
        __syncthreads();   // prior phase-2 readers done with KVs/Ps
        // load K tile
        {
            const float* kbase = qkv + (size_t)(b * S_ + k0) * ROWSTRIDE + D_ + h * HD_;
            #pragma unroll
            for (int l = 0; l < 8; l++) {
                int idx = tid + l * 256;
                int m   = idx >> 5;
                int d4  = (idx & 31) << 2;
                *(float4*)&KVs[m * QPAD + d4] =
                    *(const float4*)&kbase[(size_t)m * ROWSTRIDE + d4];
            }
        }
        __syncthreads();

        // phase 1: scores
        float c[4][4];
        #pragma unroll
        for (int i = 0; i < 4; i++)
            #pragma unroll
            for (int j = 0; j < 4; j++) c[i][j] = 0.f;

        #pragma unroll 4
        for (int d4 = 0; d4 < HD_; d4 += 4) {
            float4 qv[4], kv[4];
            #pragma unroll
            for (int i = 0; i < 4; i++)
                qv[i] = *(const float4*)&Qs[(ty + 16 * i) * QPAD + d4];
            #pragma unroll
            for (int j = 0; j < 4; j++)
                kv[j] = *(const float4*)&KVs[(tx + 16 * j) * QPAD + d4];
            #pragma unroll
            for (int i = 0; i < 4; i++)
                #pragma unroll
                for (int j = 0; j < 4; j++) {
                    c[i][j] = fmaf(qv[i].x, kv[j].x, c[i][j]);
                    c[i][j] = fmaf(qv[i].y, kv[j].y, c[i][j]);
                    c[i][j] = fmaf(qv[i].z, kv[j].z, c[i][j]);
                    c[i][j] = fmaf(qv[i].w, kv[j].w, c[i][j]);
                }
        }

        // bias: alibi[h, q, k] + pad[b, k]
        float padv[4];
        #pragma unroll
        for (int j = 0; j < 4; j++)
            padv[j] = pad[b * S_ + k0 + tx + 16 * j];
        #pragma unroll
        for (int i = 0; i < 4; i++) {
            const float* arow = alibi + (size_t)h * S_ * S_
                              + (size_t)(q0 + ty + 16 * i) * S_ + k0;
            #pragma unroll
            for (int j = 0; j < 4; j++)
                c[i][j] = fmaf(c[i][j], sscale, arow[tx + 16 * j] + padv[j]);
        }

        // online softmax (row owned by 16 lanes sharing ty)
        #pragma unroll
        for (int i = 0; i < 4; i++) {
            float tm = fmaxf(fmaxf(c[i][0], c[i][1]), fmaxf(c[i][2], c[i][3]));
            #pragma unroll
            for (int off = 1; off < 16; off <<= 1)
                tm = fmaxf(tm, __shfl_xor_sync(0xffffffffu, tm, off));
            float mn = fmaxf(m_cur[i], tm);
            float ps = 0.f;
            #pragma unroll
            for (int j = 0; j < 4; j++) {
                c[i][j] = __expf(c[i][j] - mn);
                ps += c[i][j];
            }
            #pragma unroll
            for (int off = 1; off < 16; off <<= 1)
                ps += __shfl_xor_sync(0xffffffffu, ps, off);
            float corr = __expf(m_cur[i] - mn);
            l_cur[i] = l_cur[i] * corr + ps;
            m_cur[i] = mn;
            #pragma unroll
            for (int jj = 0; jj < 8; jj++) o[i][jj] *= corr;
            // store P tile
            #pragma unroll
            for (int j = 0; j < 4; j++)
                Ps[(ty + 16 * i) * PPAD + tx + 16 * j] = c[i][j];
        }

        __syncthreads();   // Ps written; K reads done -> reuse KVs for V
        // load V tile
        {
            const float* vbase = qkv + (size_t)(b * S_ + k0) * ROWSTRIDE + 2 * D_ + h * HD_;
            #pragma unroll
            for (int l = 0; l < 8; l++) {
                int idx = tid + l * 256;
                int m   = idx >> 5;
                int d4  = (idx & 31) << 2;
                *(float4*)&KVs[m * QPAD + d4] =
                    *(const float4*)&vbase[(size_t)m * ROWSTRIDE + d4];
            }
        }
        __syncthreads();

        // phase 2: O += P @ V
        #pragma unroll 4
        for (int n = 0; n < 64; n++) {
            float4 v0 = *(const float4*)&KVs[n * QPAD + 4 * tx];
            float4 v1 = *(const float4*)&KVs[n * QPAD + 64 + 4 * tx];
            #pragma unroll
            for (int i = 0; i < 4; i++) {
                float p = Ps[(ty + 16 * i) * PPAD + n];
                o[i][0] = fmaf(p, v0.x, o[i][0]);
                o[i][1] = fmaf(p, v0.y, o[i][1]);
                o[i][2] = fmaf(p, v0.z, o[i][2]);
                o[i][3] = fmaf(p, v0.w, o[i][3]);
                o[i][4] = fmaf(p, v1.x, o[i][4]);
                o[i][5] = fmaf(p, v1.y, o[i][5]);
                o[i][6] = fmaf(p, v1.z, o[i][6]);
                o[i][7] = fmaf(p, v1.w, o[i][7]);
            }
        }
    }

    // epilogue: normalize and write [b, q, h*128 + d]
    #pragma unroll
    for (int i = 0; i < 4; i++) {
        float inv = 1.0f / l_cur[i];
        size_t row = (size_t)(b * S_ + q0 + ty + 16 * i) * D_ + h * HD_;
        float4 w0, w1;
        w0.x = o[i][0] * inv; w0.y = o[i][1] * inv;
        w0.z = o[i][2] * inv; w0.w = o[i][3] * inv;
        w1.x = o[i][4] * inv; w1.y = o[i][5] * inv;
        w1.z = o[i][6] * inv; w1.w = o[i][7] * inv;
        *(float4*)&out[row + 4 * tx]      = w0;
        *(float4*)&out[row + 64 + 4 * tx] = w1;
    }
}

// ---------------------------------------------------------------------------
// kernel_launch
// ---------------------------------------------------------------------------
extern "C" void kernel_launch(void* const* d_in, const int* in_sizes, int n_in,
                              void* d_out, int out_size)
{
    const float* x     = (const float*)d_in[0];
    const float* alibi = (const float*)d_in[1];
    const float* pad   = (const float*)d_in[2];
    const float* Wqkv  = (const float*)d_in[3];
    const float* Aqkv  = (const float*)d_in[4];
    const float* Bqkv  = (const float*)d_in[5];
    const float* Wout  = (const float*)d_in[6];
    const float* Aout  = (const float*)d_in[7];
    const float* Bout  = (const float*)d_in[8];
    float* out = (float*)d_out;

    float *qkv_p, *attn_p, *t1_p, *t2_p;
    cudaGetSymbolAddress((void**)&qkv_p,  g_qkv);
    cudaGetSymbolAddress((void**)&attn_p, g_attn);
    cudaGetSymbolAddress((void**)&t1_p,   g_t1);
    cudaGetSymbolAddress((void**)&t2_p,   g_t2);

    cudaFuncSetAttribute(attn_kernel,
                         cudaFuncAttributeMaxDynamicSharedMemorySize,
                         ATTN_SMEM_BYTES);

    // 1) t1 = x @ Aqkv
    lora_down_kernel<<<M_TOK / 32, 256>>>(x, Aqkv, t1_p, M_TOK, D_);

    // 2) qkv = x @ Wqkv^T + t1 @ Bqkv * (1/32)
    {
        dim3 grid((3 * D_) / GBN, M_TOK / GBM);
        sgemm_nt_lora<<<grid, 256>>>(x, Wqkv, t1_p, Bqkv, qkv_p,
                                     M_TOK, 3 * D_, D_, LORA_SCALE);
    }

    // 3) attention
    {
        dim3 grid(S_ / 64, H_, B_);
        attn_kernel<<<grid, 256, ATTN_SMEM_BYTES>>>(qkv_p, alibi, pad, attn_p);
    }

    // 4) t2 = attn @ Aout
    lora_down_kernel<<<M_TOK / 32, 256>>>(attn_p, Aout, t2_p, M_TOK, D_);

    // 5) out = attn @ Wout^T + t2 @ Bout * (1/32)
    {
        dim3 grid(D_ / GBN, M_TOK / GBM);
        sgemm_nt_lora<<<grid, 256>>>(attn_p, Wout, t2_p, Bout, out,
                                     M_TOK, D_, D_, LORA_SCALE);
    }
}

// round 3
// speedup vs baseline: 1.2476x; 1.2476x over previous
#include <cuda_runtime.h>
#include <cstdint>

// Problem constants
#define B_   2
#define S_   2048
#define D_   2048
#define H_   16
#define HD_  128
#define R_   32
#define M_TOK (B_ * S_)              // 4096 tokens
#define LORA_SCALE (1.0f / 32.0f)

// ---------------------------------------------------------------------------
// Scratch (allocation-free rule: __device__ globals)
// ---------------------------------------------------------------------------
static __device__ float g_qkv[M_TOK * 3 * D_];   // [4096, 6144]
static __device__ float g_attn[M_TOK * D_];      // [4096, 2048]
static __device__ float g_t1[M_TOK * R_];
static __device__ float g_t2[M_TOK * R_];

// ---------------------------------------------------------------------------
// helpers
// ---------------------------------------------------------------------------
__device__ __forceinline__ uint32_t smem_u32(const void* p) {
    uint32_t a;
    asm("{ .reg .u64 t; cvta.to.shared.u64 t, %1; cvt.u32.u64 %0, t; }"
        : "=r"(a) : "l"(p));
    return a;
}
__device__ __forceinline__ void cp16(uint32_t dst, const void* src) {
    asm volatile("cp.async.cg.shared.global [%0], [%1], 16;"
                 :: "r"(dst), "l"(src) : "memory");
}
__device__ __forceinline__ void cp_commit() {
    asm volatile("cp.async.commit_group;" ::: "memory");
}
__device__ __forceinline__ void cp_wait2() {
    asm volatile("cp.async.wait_group 2;" ::: "memory");
}
// m16n8k8 tf32 mma, accumulate in place
__device__ __forceinline__ void mma8(float* c,
                                     uint32_t a0, uint32_t a1, uint32_t a2, uint32_t a3,
                                     uint32_t b0, uint32_t b1) {
    asm volatile(
        "mma.sync.aligned.m16n8k8.row.col.f32.tf32.tf32.f32 "
        "{%0,%1,%2,%3}, {%4,%5,%6,%7}, {%8,%9}, {%0,%1,%2,%3};\n"
        : "+f"(c[0]), "+f"(c[1]), "+f"(c[2]), "+f"(c[3])
        : "r"(a0), "r"(a1), "r"(a2), "r"(a3), "r"(b0), "r"(b1));
}
__device__ __forceinline__ void split_tf32(uint32_t raw, uint32_t& hi, uint32_t& lo) {
    hi = raw & 0xffffe000u;
    lo = __float_as_uint(__uint_as_float(raw) - __uint_as_float(hi));
}

// ---------------------------------------------------------------------------
// tf32x3 fused GEMM (mma.sync):
//   C[M,N] = A[M,K] @ W[N,K]^T + T[M,32] @ Bq[32,N] * lscale
// CTA 128x128; chunk K=16; 4-stage cp.async pipeline.
// smem per stage: A[128][20] + B[128][20] fp32 (pad 20 -> conflict-free frags)
// ---------------------------------------------------------------------------
#define CH      16
#define ROWPAD  20
#define STAGE_F (2 * 128 * ROWPAD)          // floats per stage (A+B)
#define NSTAGE  4
#define TCG_SMEM (NSTAGE * STAGE_F * 4)     // 81920 bytes

__global__ void __launch_bounds__(256, 2) tc_gemm_lora(
    const float* __restrict__ A, const float* __restrict__ W,
    const float* __restrict__ T, const float* __restrict__ Bq,
    float* __restrict__ C, int M, int N, int K, float lscale)
{
    extern __shared__ __align__(16) float smf[];
    const uint32_t sbase = smem_u32(smf);

    const int tid  = threadIdx.x;
    const int wid  = tid >> 5;
    const int lane = tid & 31;
    const int g    = lane >> 2;          // 0..7
    const int q    = lane & 3;           // 0..3
    const int warpM = (wid & 1) * 64;
    const int warpN = (wid >> 1) * 32;

    const int n0 = blockIdx.x * 128;
    const int m0 = blockIdx.y * 128;

    const int kc    = K / CH;            // main chunks
    const int total = kc + 2;            // + 2 LoRA chunks (R=32)

    float acc[4][4][4];
    #pragma unroll
    for (int i = 0; i < 4; i++)
        #pragma unroll
        for (int j = 0; j < 4; j++)
            #pragma unroll
            for (int e = 0; e < 4; e++) acc[i][j][e] = 0.f;

    // ---- producer: issue chunk c into stage s ----
    auto issue = [&](int c, int s) {
        const uint32_t aS = sbase + (uint32_t)(s * STAGE_F) * 4u;
        const uint32_t bS = aS + 128u * ROWPAD * 4u;
        if (c < kc) {
            const int k0 = c * CH;
            #pragma unroll
            for (int j = 0; j < 2; j++) {
                int idx = tid + j * 256;
                int r   = idx >> 2;               // 0..127
                int kq  = (idx & 3) << 2;         // 0,4,8,12
                cp16(aS + (uint32_t)(r * ROWPAD + kq) * 4u,
                     &A[(size_t)(m0 + r) * K + k0 + kq]);
                cp16(bS + (uint32_t)(r * ROWPAD + kq) * 4u,
                     &W[(size_t)(n0 + r) * K + k0 + kq]);
            }
        } else {
            const int kl0 = (c - kc) * CH;
            #pragma unroll
            for (int j = 0; j < 2; j++) {
                int idx = tid + j * 256;
                int r   = idx >> 2;
                int kq  = (idx & 3) << 2;
                cp16(aS + (uint32_t)(r * ROWPAD + kq) * 4u,
                     &T[(size_t)(m0 + r) * 32 + kl0 + kq]);
            }
            // B side: Bs[n][k] = Bq[kl0+k][n0+n] * lscale (scalar, coalesced LDG)
            float* bptr = smf + (size_t)s * STAGE_F + 128 * ROWPAD;
            #pragma unroll
            for (int j = 0; j < 8; j++) {
                int idx = tid + j * 256;           // 0..2047
                int n   = idx & 127;
                int k   = idx >> 7;                // 0..15
                bptr[n * ROWPAD + k] =
                    Bq[(size_t)(kl0 + k) * N + n0 + n] * lscale;
            }
        }
        cp_commit();
    };

    // prologue: stages 0..2 <- chunks 0..2
    issue(0, 0); issue(1, 1); issue(2, 2);

    for (int i = 0; i < total; i++) {
        cp_wait2();
        __syncthreads();

        const bool lora = (i >= kc);
        const float* Ab = smf + (size_t)(i & 3) * STAGE_F;
        const float* Bb = Ab + 128 * ROWPAD;

        #pragma unroll
        for (int ks = 0; ks < CH; ks += 8) {
            // B fragments for 4 n-tiles
            uint32_t bh0[4], bh1[4], bl0[4], bl1[4];
            #pragma unroll
            for (int nt = 0; nt < 4; nt++) {
                int n = warpN + nt * 8 + g;
                uint32_t r0 = __float_as_uint(Bb[n * ROWPAD + ks + q]);
                uint32_t r1 = __float_as_uint(Bb[n * ROWPAD + ks + q + 4]);
                if (!lora) { split_tf32(r0, bh0[nt], bl0[nt]);
                             split_tf32(r1, bh1[nt], bl1[nt]); }
                else       { bh0[nt] = r0; bh1[nt] = r1; }
            }
            #pragma unroll
            for (int mh = 0; mh < 4; mh += 2) {
                uint32_t ah[2][4], al[2][4];
                #pragma unroll
                for (int t = 0; t < 2; t++) {
                    int m = warpM + (mh + t) * 16 + g;
                    uint32_t r0 = __float_as_uint(Ab[m * ROWPAD + ks + q]);
                    uint32_t r1 = __float_as_uint(Ab[(m + 8) * ROWPAD + ks + q]);
                    uint32_t r2 = __float_as_uint(Ab[m * ROWPAD + ks + q + 4]);
                    uint32_t r3 = __float_as_uint(Ab[(m + 8) * ROWPAD + ks + q + 4]);
                    if (!lora) {
                        split_tf32(r0, ah[t][0], al[t][0]);
                        split_tf32(r1, ah[t][1], al[t][1]);
                        split_tf32(r2, ah[t][2], al[t][2]);
                        split_tf32(r3, ah[t][3], al[t][3]);
                    } else {
                        ah[t][0] = r0; ah[t][1] = r1; ah[t][2] = r2; ah[t][3] = r3;
                    }
                }
                #pragma unroll
                for (int t = 0; t < 2; t++)
                    #pragma unroll
                    for (int nt = 0; nt < 4; nt++) {
                        float* c = acc[mh + t][nt];
                        mma8(c, ah[t][0], ah[t][1], ah[t][2], ah[t][3],
                             bh0[nt], bh1[nt]);
                        if (!lora) {
                            mma8(c, al[t][0], al[t][1], al[t][2], al[t][3],
                                 bh0[nt], bh1[nt]);
                            mma8(c, ah[t][0], ah[t][1], ah[t][2], ah[t][3],
                                 bl0[nt], bl1[nt]);
                        }
                    }
            }
        }

        int nxt = i + 3;
        if (nxt < total) issue(nxt, nxt & 3);
        else cp_commit();   // keep group accounting aligned
    }

    // epilogue
    #pragma unroll
    for (int mt = 0; mt < 4; mt++) {
        int row = m0 + warpM + mt * 16 + g;
        #pragma unroll
        for (int nt = 0; nt < 4; nt++) {
            int col = n0 + warpN + nt * 8 + 2 * q;
            float2 v0 = make_float2(acc[mt][nt][0], acc[mt][nt][1]);
            float2 v1 = make_float2(acc[mt][nt][2], acc[mt][nt][3]);
            *(float2*)&C[(size_t)row * N + col]       = v0;
            *(float2*)&C[(size_t)(row + 8) * N + col] = v1;
        }
    }
}

// ---------------------------------------------------------------------------
// Small LoRA-down GEMM: T[M,32] = X[M,K] @ A[K,32]
// ---------------------------------------------------------------------------
__global__ void __launch_bounds__(256) lora_down_kernel(
    const float* __restrict__ X, const float* __restrict__ Amat,
    float* __restrict__ Tout, int M, int K)
{
    __shared__ __align__(16) float Xs[32][68];
    __shared__ __align__(16) float As2[64][36];

    const int tid = threadIdx.x;
    const int m0  = blockIdx.x * 32;
    const int n   = tid & 31;
    const int mq  = (tid >> 5) * 4;

    float acc[4] = {0.f, 0.f, 0.f, 0.f};

    for (int k0 = 0; k0 < K; k0 += 64) {
        __syncthreads();
        #pragma unroll
        for (int l = 0; l < 2; l++) {
            int idx = tid + l * 256;
            int m   = idx >> 4;
            int k4  = (idx & 15) << 2;
            *(float4*)&Xs[m][k4] =
                *(const float4*)&X[(size_t)(m0 + m) * K + k0 + k4];
        }
        #pragma unroll
        for (int l = 0; l < 2; l++) {
            int idx = tid + l * 256;
            int kk  = idx >> 3;
            int n4  = (idx & 7) << 2;
            *(float4*)&As2[kk][n4] =
                *(const float4*)&Amat[(size_t)(k0 + kk) * 32 + n4];
        }
        __syncthreads();
        #pragma unroll 16
        for (int kk = 0; kk < 64; kk++) {
            float a = As2[kk][n];
            acc[0] = fmaf(Xs[mq + 0][kk], a, acc[0]);
            acc[1] = fmaf(Xs[mq + 1][kk], a, acc[1]);
            acc[2] = fmaf(Xs[mq + 2][kk], a, acc[2]);
            acc[3] = fmaf(Xs[mq + 3][kk], a, acc[3]);
        }
    }
    #pragma unroll
    for (int i = 0; i < 4; i++)
        Tout[(size_t)(m0 + mq + i) * 32 + n] = acc[i];
}

// ---------------------------------------------------------------------------
// Flash attention (fp32, online softmax) — unchanged from round 1 (passing)
// ---------------------------------------------------------------------------
#define QPAD 132
#define PPAD 68
#define ATTN_SMEM_BYTES ((2 * 64 * QPAD + 64 * PPAD) * 4)

__global__ void __launch_bounds__(256, 2) attn_kernel(
    const float* __restrict__ qkv, const float* __restrict__ alibi,
    const float* __restrict__ pad, float* __restrict__ out)
{
    extern __shared__ __align__(16) float sm[];
    float* Qs  = sm;
    float* KVs = sm + 64 * QPAD;
    float* Ps  = sm + 2 * 64 * QPAD;

    const int q0 = blockIdx.x * 64;
    const int h  = blockIdx.y;
    const int b  = blockIdx.z;
    const int tid = threadIdx.x;
    const int tx = tid & 15;
    const int ty = tid >> 4;

    const int ROWSTRIDE = 3 * D_;

    {
        const float* qbase = qkv + (size_t)(b * S_ + q0) * ROWSTRIDE + h * HD_;
        #pragma unroll
        for (int l = 0; l < 8; l++) {
            int idx = tid + l * 256;
            int m   = idx >> 5;
            int d4  = (idx & 31) << 2;
            *(float4*)&Qs[m * QPAD + d4] =
                *(const float4*)&qbase[(size_t)m * ROWSTRIDE + d4];
        }
    }

    float m_cur[4], l_cur[4], o[4][8];
    #pragma unroll
    for (int i = 0; i < 4; i++) {
        m_cur[i] = -1e30f; l_cur[i] = 0.f;
        #pragma unroll
        for (int jj = 0; jj < 8; jj++) o[i][jj] = 0.f;
    }

    const float sscale = 0.08838834764831845f;

    for (int kt = 0; kt < S_ / 64; kt++) {
        const int k0 = kt * 64;
        __syncthreads();
        {
            const float* kbase = qkv + (size_t)(b * S_ + k0) * ROWSTRIDE + D_ + h * HD_;
            #pragma unroll
            for (int l = 0; l < 8; l++) {
                int idx = tid + l * 256;
                int m   = idx >> 5;
                int d4  = (idx & 31) << 2;
                *(float4*)&KVs[m * QPAD + d4] =
                    *(const float4*)&kbase[(size_t)m * ROWSTRIDE + d4];
            }
        }
        __syncthreads();

        float c[4][4];
        #pragma unroll
        for (int i = 0; i < 4; i++)
            #pragma unroll
            for (int j = 0; j < 4; j++) c[i][j] = 0.f;

        #pragma unroll 4
        for (int d4 = 0; d4 < HD_; d4 += 4) {
            float4 qv[4], kv[4];
            #pragma unroll
            for (int i = 0; i < 4; i++)
                qv[i] = *(const float4*)&Qs[(ty + 16 * i) * QPAD + d4];
            #pragma unroll
            for (int j = 0; j < 4; j++)
                kv[j] = *(const float4*)&KVs[(tx + 16 * j) * QPAD + d4];
            #pragma unroll
            for (int i = 0; i < 4; i++)
                #pragma unroll
                for (int j = 0; j < 4; j++) {
                    c[i][j] = fmaf(qv[i].x, kv[j].x, c[i][j]);
                    c[i][j] = fmaf(qv[i].y, kv[j].y, c[i][j]);
                    c[i][j] = fmaf(qv[i].z, kv[j].z, c[i][j]);
                    c[i][j] = fmaf(qv[i].w, kv[j].w, c[i][j]);
                }
        }

        float padv[4];
        #pragma unroll
        for (int j = 0; j < 4; j++)
            padv[j] = pad[b * S_ + k0 + tx + 16 * j];
        #pragma unroll
        for (int i = 0; i < 4; i++) {
            const float* arow = alibi + (size_t)h * S_ * S_
                              + (size_t)(q0 + ty + 16 * i) * S_ + k0;
            #pragma unroll
            for (int j = 0; j < 4; j++)
                c[i][j] = fmaf(c[i][j], sscale, arow[tx + 16 * j] + padv[j]);
        }

        #pragma unroll
        for (int i = 0; i < 4; i++) {
            float tm = fmaxf(fmaxf(c[i][0], c[i][1]), fmaxf(c[i][2], c[i][3]));
            #pragma unroll
            for (int off = 1; off < 16; off <<= 1)
                tm = fmaxf(tm, __shfl_xor_sync(0xffffffffu, tm, off));
            float mn = fmaxf(m_cur[i], tm);
            float ps = 0.f;
            #pragma unroll
            for (int j = 0; j < 4; j++) {
                c[i][j] = __expf(c[i][j] - mn);
                ps += c[i][j];
            }
            #pragma unroll
            for (int off = 1; off < 16; off <<= 1)
                ps += __shfl_xor_sync(0xffffffffu, ps, off);
            float corr = __expf(m_cur[i] - mn);
            l_cur[i] = l_cur[i] * corr + ps;
            m_cur[i] = mn;
            #pragma unroll
            for (int jj = 0; jj < 8; jj++) o[i][jj] *= corr;
            #pragma unroll
            for (int j = 0; j < 4; j++)
                Ps[(ty + 16 * i) * PPAD + tx + 16 * j] = c[i][j];
        }

        __syncthreads();
        {
            const float* vbase = qkv + (size_t)(b * S_ + k0) * ROWSTRIDE + 2 * D_ + h * HD_;
            #pragma unroll
            for (int l = 0; l < 8; l++) {
                int idx = tid + l * 256;
                int m   = idx >> 5;
                int d4  = (idx & 31) << 2;
                *(float4*)&KVs[m * QPAD + d4] =
                    *(const float4*)&vbase[(size_t)m * ROWSTRIDE + d4];
            }
        }
        __syncthreads();

        #pragma unroll 4
        for (int n = 0; n < 64; n++) {
            float4 v0 = *(const float4*)&KVs[n * QPAD + 4 * tx];
            float4 v1 = *(const float4*)&KVs[n * QPAD + 64 + 4 * tx];
            #pragma unroll
            for (int i = 0; i < 4; i++) {
                float p = Ps[(ty + 16 * i) * PPAD + n];
                o[i][0] = fmaf(p, v0.x, o[i][0]);
                o[i][1] = fmaf(p, v0.y, o[i][1]);
                o[i][2] = fmaf(p, v0.z, o[i][2]);
                o[i][3] = fmaf(p, v0.w, o[i][3]);
                o[i][4] = fmaf(p, v1.x, o[i][4]);
                o[i][5] = fmaf(p, v1.y, o[i][5]);
                o[i][6] = fmaf(p, v1.z, o[i][6]);
                o[i][7] = fmaf(p, v1.w, o[i][7]);
            }
        }
    }

    #pragma unroll
    for (int i = 0; i < 4; i++) {
        float inv = 1.0f / l_cur[i];
        size_t row = (size_t)(b * S_ + q0 + ty + 16 * i) * D_ + h * HD_;
        float4 w0, w1;
        w0.x = o[i][0] * inv; w0.y = o[i][1] * inv;
        w0.z = o[i][2] * inv; w0.w = o[i][3] * inv;
        w1.x = o[i][4] * inv; w1.y = o[i][5] * inv;
        w1.z = o[i][6] * inv; w1.w = o[i][7] * inv;
        *(float4*)&out[row + 4 * tx]      = w0;
        *(float4*)&out[row + 64 + 4 * tx] = w1;
    }
}

// ---------------------------------------------------------------------------
// kernel_launch
// ---------------------------------------------------------------------------
extern "C" void kernel_launch(void* const* d_in, const int* in_sizes, int n_in,
                              void* d_out, int out_size)
{
    const float* x     = (const float*)d_in[0];
    const float* alibi = (const float*)d_in[1];
    const float* pad   = (const float*)d_in[2];
    const float* Wqkv  = (const float*)d_in[3];
    const float* Aqkv  = (const float*)d_in[4];
    const float* Bqkv  = (const float*)d_in[5];
    const float* Wout  = (const float*)d_in[6];
    const float* Aout  = (const float*)d_in[7];
    const float* Bout  = (const float*)d_in[8];
    float* out = (float*)d_out;

    float *qkv_p, *attn_p, *t1_p, *t2_p;
    cudaGetSymbolAddress((void**)&qkv_p,  g_qkv);
    cudaGetSymbolAddress((void**)&attn_p, g_attn);
    cudaGetSymbolAddress((void**)&t1_p,   g_t1);
    cudaGetSymbolAddress((void**)&t2_p,   g_t2);

    cudaFuncSetAttribute(attn_kernel,
                         cudaFuncAttributeMaxDynamicSharedMemorySize,
                         ATTN_SMEM_BYTES);
    cudaFuncSetAttribute(tc_gemm_lora,
                         cudaFuncAttributeMaxDynamicSharedMemorySize,
                         TCG_SMEM);

    // 1) t1 = x @ Aqkv
    lora_down_kernel<<<M_TOK / 32, 256>>>(x, Aqkv, t1_p, M_TOK, D_);

    // 2) qkv = x @ Wqkv^T + t1 @ Bqkv * (1/32)   (mma.sync tf32x3)
    {
        dim3 grid((3 * D_) / 128, M_TOK / 128);
        tc_gemm_lora<<<grid, 256, TCG_SMEM>>>(x, Wqkv, t1_p, Bqkv, qkv_p,
                                              M_TOK, 3 * D_, D_, LORA_SCALE);
    }

    // 3) attention
    {
        dim3 grid(S_ / 64, H_, B_);
        attn_kernel<<<grid, 256, ATTN_SMEM_BYTES>>>(qkv_p, alibi, pad, attn_p);
    }

    // 4) t2 = attn @ Aout
    lora_down_kernel<<<M_TOK / 32, 256>>>(attn_p, Aout, t2_p, M_TOK, D_);

    // 5) out = attn @ Wout^T + t2 @ Bout * (1/32)   (mma.sync tf32x3)
    {
        dim3 grid(D_ / 128, M_TOK / 128);
        tc_gemm_lora<<<grid, 256, TCG_SMEM>>>(attn_p, Wout, t2_p, Bout, out,
                                              M_TOK, D_, D_, LORA_SCALE);
    }
}

// round 4
// speedup vs baseline: 1.4586x; 1.1691x over previous
#include <cuda_runtime.h>
#include <cuda_bf16.h>
#include <cstdint>

// Problem constants
#define B_   2
#define S_   2048
#define D_   2048
#define H_   16
#define HD_  128
#define R_   32
#define M_TOK (B_ * S_)              // 4096 tokens
#define LORA_SCALE (1.0f / 32.0f)

// ---------------------------------------------------------------------------
// Scratch (allocation-free rule: __device__ globals)
// ---------------------------------------------------------------------------
static __device__ float g_qkv[M_TOK * 3 * D_];   // fp32 qkv (attention input)
static __device__ float g_attn[M_TOK * D_];      // fp32 attention output

static __device__ __align__(16) __nv_bfloat16 g_xh[M_TOK * D_];
static __device__ __align__(16) __nv_bfloat16 g_xl[M_TOK * D_];
static __device__ __align__(16) __nv_bfloat16 g_wqh[3 * D_ * D_];
static __device__ __align__(16) __nv_bfloat16 g_wql[3 * D_ * D_];
static __device__ __align__(16) __nv_bfloat16 g_woh[D_ * D_];
static __device__ __align__(16) __nv_bfloat16 g_wol[D_ * D_];
static __device__ __align__(16) __nv_bfloat16 g_ah[M_TOK * D_];
static __device__ __align__(16) __nv_bfloat16 g_al[M_TOK * D_];
static __device__ __align__(16) __nv_bfloat16 g_bqt[3 * D_ * R_];   // [6144][32]
static __device__ __align__(16) __nv_bfloat16 g_bot[D_ * R_];       // [2048][32]
static __device__ __align__(16) __nv_bfloat16 g_t1h[M_TOK * R_];
static __device__ __align__(16) __nv_bfloat16 g_t2h[M_TOK * R_];

// ---------------------------------------------------------------------------
// helpers
// ---------------------------------------------------------------------------
__device__ __forceinline__ uint32_t smem_u32(const void* p) {
    uint32_t a;
    asm("{ .reg .u64 t; cvta.to.shared.u64 t, %1; cvt.u32.u64 %0, t; }"
        : "=r"(a) : "l"(p));
    return a;
}
__device__ __forceinline__ void cp16(uint32_t dst, const void* src) {
    asm volatile("cp.async.cg.shared.global [%0], [%1], 16;"
                 :: "r"(dst), "l"(src) : "memory");
}
__device__ __forceinline__ void cp_commit() {
    asm volatile("cp.async.commit_group;" ::: "memory");
}
__device__ __forceinline__ void cp_wait1() {
    asm volatile("cp.async.wait_group 1;" ::: "memory");
}
__device__ __forceinline__ void ldm4(uint32_t& r0, uint32_t& r1,
                                     uint32_t& r2, uint32_t& r3, uint32_t addr) {
    asm volatile("ldmatrix.sync.aligned.m8n8.x4.shared.b16 {%0,%1,%2,%3}, [%4];"
                 : "=r"(r0), "=r"(r1), "=r"(r2), "=r"(r3) : "r"(addr));
}
__device__ __forceinline__ void mma16(float* c, const uint32_t* a, const uint32_t* b) {
    asm volatile(
        "mma.sync.aligned.m16n8k16.row.col.f32.bf16.bf16.f32 "
        "{%0,%1,%2,%3}, {%4,%5,%6,%7}, {%8,%9}, {%0,%1,%2,%3};"
        : "+f"(c[0]), "+f"(c[1]), "+f"(c[2]), "+f"(c[3])
        : "r"(a[0]), "r"(a[1]), "r"(a[2]), "r"(a[3]), "r"(b[0]), "r"(b[1]));
}

// ---------------------------------------------------------------------------
// Pre-pass: split fp32 -> bf16 hi (truncation) + bf16 lo (RN residual)
// ---------------------------------------------------------------------------
__global__ void __launch_bounds__(256) split_kernel(
    const float4* __restrict__ src, uint2* __restrict__ hi,
    uint2* __restrict__ lo, int n4)
{
    int i = blockIdx.x * 256 + threadIdx.x;
    if (i >= n4) return;
    float4 v = src[i];
    uint32_t ux = __float_as_uint(v.x), uy = __float_as_uint(v.y);
    uint32_t uz = __float_as_uint(v.z), uw = __float_as_uint(v.w);
    uint32_t h0 = (uy & 0xffff0000u) | (ux >> 16);
    uint32_t h1 = (uw & 0xffff0000u) | (uz >> 16);
    float lx = v.x - __uint_as_float(ux & 0xffff0000u);
    float ly = v.y - __uint_as_float(uy & 0xffff0000u);
    float lz = v.z - __uint_as_float(uz & 0xffff0000u);
    float lw = v.w - __uint_as_float(uw & 0xffff0000u);
    __nv_bfloat162 l0 = __floats2bfloat162_rn(lx, ly);
    __nv_bfloat162 l1 = __floats2bfloat162_rn(lz, lw);
    hi[i] = make_uint2(h0, h1);
    lo[i] = make_uint2(*(uint32_t*)&l0, *(uint32_t*)&l1);
}

// Pre-pass: Bq[32,N] -> out[N][32] bf16(RN), scaled
__global__ void __launch_bounds__(256) transpose_scale_kernel(
    const float* __restrict__ Bq, __nv_bfloat16* __restrict__ out,
    int N, float scale)
{
    int idx = blockIdx.x * 256 + threadIdx.x;   // total N*32
    int k = idx & 31;
    int n = idx >> 5;
    if (n < N)
        out[(size_t)n * 32 + k] = __float2bfloat16(Bq[(size_t)k * N + n] * scale);
}

// ---------------------------------------------------------------------------
// Pure-bf16 fused GEMM (bf16x3 via pre-split operands):
//   C[M,N] = (Ah+Al)[M,K] @ (Bh+Bl)[N,K]^T  (3 products, lo*lo dropped)
//          + T[M,32] @ Bqt[N,32]^T          (single-pass bf16 LoRA)
// CTA 128x128; chunk K=16; 3-stage cp.async pipeline; ldmatrix fragments.
// smem/stage: 4 tiles (Ah,Al,Bh,Bl) of 128 rows x 48B (32B data + pad)
// ---------------------------------------------------------------------------
#define OFF_AH 0
#define OFF_AL 6144
#define OFF_BH 12288
#define OFF_BL 18432
#define STAGE_B 24576
#define TCG_SMEM (3 * STAGE_B)      // 73728 bytes

__global__ void __launch_bounds__(256, 2) tc_gemm_bf16(
    const __nv_bfloat16* __restrict__ Ah, const __nv_bfloat16* __restrict__ Al,
    const __nv_bfloat16* __restrict__ Bh, const __nv_bfloat16* __restrict__ Bl,
    const __nv_bfloat16* __restrict__ Tm, const __nv_bfloat16* __restrict__ Bqt,
    float* __restrict__ C, int M, int N, int K)
{
    extern __shared__ __align__(128) char smem[];
    const uint32_t sbase = smem_u32(smem);

    const int tid  = threadIdx.x;
    const int wid  = tid >> 5;
    const int lane = tid & 31;
    const int g    = lane >> 2;
    const int q    = lane & 3;
    const int warpM = (wid & 1) * 64;
    const int warpN = (wid >> 1) * 32;

    const int n0 = blockIdx.x * 128;
    const int m0 = blockIdx.y * 128;

    const int kc    = K >> 4;          // main chunks of 16
    const int total = kc + 2;          // + 2 LoRA chunks (R=32)

    float acc[4][4][4];
    #pragma unroll
    for (int i = 0; i < 4; i++)
        #pragma unroll
        for (int j = 0; j < 4; j++)
            #pragma unroll
            for (int e = 0; e < 4; e++) acc[i][j][e] = 0.f;

    // producer: chunk c -> stage s (each thread: one 16B segment per tile)
    const int pr = tid >> 1;                 // row 0..127
    const int ps = tid & 1;                  // k segment 0/1
    auto issue = [&](int c, int s) {
        const uint32_t st = sbase + (uint32_t)s * STAGE_B;
        const uint32_t doff = (uint32_t)pr * 48u + (uint32_t)ps * 16u;
        if (c < kc) {
            size_t ao = (size_t)(m0 + pr) * K + c * 16 + ps * 8;
            size_t bo = (size_t)(n0 + pr) * K + c * 16 + ps * 8;
            cp16(st + OFF_AH + doff, Ah + ao);
            cp16(st + OFF_AL + doff, Al + ao);
            cp16(st + OFF_BH + doff, Bh + bo);
            cp16(st + OFF_BL + doff, Bl + bo);
        } else {
            int kl = (c - kc) * 16 + ps * 8;
            cp16(st + OFF_AH + doff, Tm  + (size_t)(m0 + pr) * 32 + kl);
            cp16(st + OFF_BH + doff, Bqt + (size_t)(n0 + pr) * 32 + kl);
        }
        cp_commit();
    };

    issue(0, 0);
    issue(1, 1);

    const int mi = lane >> 3;          // matrix index 0..3 for ldmatrix
    const int l7 = lane & 7;

    int stage = 2 % 3;   // stage of chunk i+2 (rotates)
    for (int i = 0; i < total; i++) {
        cp_wait1();
        __syncthreads();
        if (i + 2 < total) issue(i + 2, (i + 2) % 3);
        else cp_commit();

        const uint32_t st = sbase + (uint32_t)(i % 3) * STAGE_B;
        const bool lora = (i >= kc);

        // B fragments: bh[nt][2], bl[nt][2]
        uint32_t bh[4][2], bl[4][2];
        #pragma unroll
        for (int bg = 0; bg < 2; bg++) {
            uint32_t rowB = warpN + bg * 16 + ((mi >> 1) << 3) + l7;
            uint32_t addr = st + OFF_BH + rowB * 48u + (uint32_t)(mi & 1) * 16u;
            ldm4(bh[2 * bg][0], bh[2 * bg][1], bh[2 * bg + 1][0], bh[2 * bg + 1][1], addr);
            if (!lora)
                ldm4(bl[2 * bg][0], bl[2 * bg][1], bl[2 * bg + 1][0], bl[2 * bg + 1][1],
                     addr + (OFF_BL - OFF_BH));
        }
        #pragma unroll
        for (int mt = 0; mt < 4; mt++) {
            uint32_t rowA = warpM + mt * 16 + ((mi & 1) << 3) + l7;
            uint32_t addrA = st + OFF_AH + rowA * 48u + (uint32_t)(mi >> 1) * 16u;
            uint32_t ah[4], al[4];
            ldm4(ah[0], ah[1], ah[2], ah[3], addrA);
            if (!lora)
                ldm4(al[0], al[1], al[2], al[3], addrA + (OFF_AL - OFF_AH));
            #pragma unroll
            for (int nt = 0; nt < 4; nt++) {
                mma16(acc[mt][nt], ah, bh[nt]);
                if (!lora) {
                    mma16(acc[mt][nt], al, bh[nt]);
                    mma16(acc[mt][nt], ah, bl[nt]);
                }
            }
        }
        (void)stage;
    }

    // epilogue
    #pragma unroll
    for (int mt = 0; mt < 4; mt++) {
        int row = m0 + warpM + mt * 16 + g;
        #pragma unroll
        for (int nt = 0; nt < 4; nt++) {
            int col = n0 + warpN + nt * 8 + 2 * q;
            *(float2*)&C[(size_t)row * N + col] =
                make_float2(acc[mt][nt][0], acc[mt][nt][1]);
            *(float2*)&C[(size_t)(row + 8) * N + col] =
                make_float2(acc[mt][nt][2], acc[mt][nt][3]);
        }
    }
}

// ---------------------------------------------------------------------------
// Small LoRA-down GEMM: T[M,32] = X[M,K] @ A[K,32]   (writes bf16 RN)
// ---------------------------------------------------------------------------
__global__ void __launch_bounds__(256) lora_down_kernel(
    const float* __restrict__ X, const float* __restrict__ Amat,
    __nv_bfloat16* __restrict__ Tout, int M, int K)
{
    __shared__ __align__(16) float Xs[32][68];
    __shared__ __align__(16) float As2[64][36];

    const int tid = threadIdx.x;
    const int m0  = blockIdx.x * 32;
    const int n   = tid & 31;
    const int mq  = (tid >> 5) * 4;

    float acc[4] = {0.f, 0.f, 0.f, 0.f};

    for (int k0 = 0; k0 < K; k0 += 64) {
        __syncthreads();
        #pragma unroll
        for (int l = 0; l < 2; l++) {
            int idx = tid + l * 256;
            int m   = idx >> 4;
            int k4  = (idx & 15) << 2;
            *(float4*)&Xs[m][k4] =
                *(const float4*)&X[(size_t)(m0 + m) * K + k0 + k4];
        }
        #pragma unroll
        for (int l = 0; l < 2; l++) {
            int idx = tid + l * 256;
            int kk  = idx >> 3;
            int n4  = (idx & 7) << 2;
            *(float4*)&As2[kk][n4] =
                *(const float4*)&Amat[(size_t)(k0 + kk) * 32 + n4];
        }
        __syncthreads();
        #pragma unroll 16
        for (int kk = 0; kk < 64; kk++) {
            float a = As2[kk][n];
            acc[0] = fmaf(Xs[mq + 0][kk], a, acc[0]);
            acc[1] = fmaf(Xs[mq + 1][kk], a, acc[1]);
            acc[2] = fmaf(Xs[mq + 2][kk], a, acc[2]);
            acc[3] = fmaf(Xs[mq + 3][kk], a, acc[3]);
        }
    }
    #pragma unroll
    for (int i = 0; i < 4; i++)
        Tout[(size_t)(m0 + mq + i) * 32 + n] = __float2bfloat16(acc[i]);
}

// ---------------------------------------------------------------------------
// Flash attention (fp32, online softmax) — unchanged (passing)
// ---------------------------------------------------------------------------
#define QPAD 132
#define PPAD 68
#define ATTN_SMEM_BYTES ((2 * 64 * QPAD + 64 * PPAD) * 4)

__global__ void __launch_bounds__(256, 2) attn_kernel(
    const float* __restrict__ qkv, const float* __restrict__ alibi,
    const float* __restrict__ pad, float* __restrict__ out)
{
    extern __shared__ __align__(16) float sm[];
    float* Qs  = sm;
    float* KVs = sm + 64 * QPAD;
    float* Ps  = sm + 2 * 64 * QPAD;

    const int q0 = blockIdx.x * 64;
    const int h  = blockIdx.y;
    const int b  = blockIdx.z;
    const int tid = threadIdx.x;
    const int tx = tid & 15;
    const int ty = tid >> 4;

    const int ROWSTRIDE = 3 * D_;

    {
        const float* qbase = qkv + (size_t)(b * S_ + q0) * ROWSTRIDE + h * HD_;
        #pragma unroll
        for (int l = 0; l < 8; l++) {
            int idx = tid + l * 256;
            int m   = idx >> 5;
            int d4  = (idx & 31) << 2;
            *(float4*)&Qs[m * QPAD + d4] =
                *(const float4*)&qbase[(size_t)m * ROWSTRIDE + d4];
        }
    }

    float m_cur[4], l_cur[4], o[4][8];
    #pragma unroll
    for (int i = 0; i < 4; i++) {
        m_cur[i] = -1e30f; l_cur[i] = 0.f;
        #pragma unroll
        for (int jj = 0; jj < 8; jj++) o[i][jj] = 0.f;
    }

    const float sscale = 0.08838834764831845f;

    for (int kt = 0; kt < S_ / 64; kt++) {
        const int k0 = kt * 64;
        __syncthreads();
        {
            const float* kbase = qkv + (size_t)(b * S_ + k0) * ROWSTRIDE + D_ + h * HD_;
            #pragma unroll
            for (int l = 0; l < 8; l++) {
                int idx = tid + l * 256;
                int m   = idx >> 5;
                int d4  = (idx & 31) << 2;
                *(float4*)&KVs[m * QPAD + d4] =
                    *(const float4*)&kbase[(size_t)m * ROWSTRIDE + d4];
            }
        }
        __syncthreads();

        float c[4][4];
        #pragma unroll
        for (int i = 0; i < 4; i++)
            #pragma unroll
            for (int j = 0; j < 4; j++) c[i][j] = 0.f;

        #pragma unroll 4
        for (int d4 = 0; d4 < HD_; d4 += 4) {
            float4 qv[4], kv[4];
            #pragma unroll
            for (int i = 0; i < 4; i++)
                qv[i] = *(const float4*)&Qs[(ty + 16 * i) * QPAD + d4];
            #pragma unroll
            for (int j = 0; j < 4; j++)
                kv[j] = *(const float4*)&KVs[(tx + 16 * j) * QPAD + d4];
            #pragma unroll
            for (int i = 0; i < 4; i++)
                #pragma unroll
                for (int j = 0; j < 4; j++) {
                    c[i][j] = fmaf(qv[i].x, kv[j].x, c[i][j]);
                    c[i][j] = fmaf(qv[i].y, kv[j].y, c[i][j]);
                    c[i][j] = fmaf(qv[i].z, kv[j].z, c[i][j]);
                    c[i][j] = fmaf(qv[i].w, kv[j].w, c[i][j]);
                }
        }

        float padv[4];
        #pragma unroll
        for (int j = 0; j < 4; j++)
            padv[j] = pad[b * S_ + k0 + tx + 16 * j];
        #pragma unroll
        for (int i = 0; i < 4; i++) {
            const float* arow = alibi + (size_t)h * S_ * S_
                              + (size_t)(q0 + ty + 16 * i) * S_ + k0;
            #pragma unroll
            for (int j = 0; j < 4; j++)
                c[i][j] = fmaf(c[i][j], sscale, arow[tx + 16 * j] + padv[j]);
        }

        #pragma unroll
        for (int i = 0; i < 4; i++) {
            float tm = fmaxf(fmaxf(c[i][0], c[i][1]), fmaxf(c[i][2], c[i][3]));
            #pragma unroll
            for (int off = 1; off < 16; off <<= 1)
                tm = fmaxf(tm, __shfl_xor_sync(0xffffffffu, tm, off));
            float mn = fmaxf(m_cur[i], tm);
            float ps = 0.f;
            #pragma unroll
            for (int j = 0; j < 4; j++) {
                c[i][j] = __expf(c[i][j] - mn);
                ps += c[i][j];
            }
            #pragma unroll
            for (int off = 1; off < 16; off <<= 1)
                ps += __shfl_xor_sync(0xffffffffu, ps, off);
            float corr = __expf(m_cur[i] - mn);
            l_cur[i] = l_cur[i] * corr + ps;
            m_cur[i] = mn;
            #pragma unroll
            for (int jj = 0; jj < 8; jj++) o[i][jj] *= corr;
            #pragma unroll
            for (int j = 0; j < 4; j++)
                Ps[(ty + 16 * i) * PPAD + tx + 16 * j] = c[i][j];
        }

        __syncthreads();
        {
            const float* vbase = qkv + (size_t)(b * S_ + k0) * ROWSTRIDE + 2 * D_ + h * HD_;
            #pragma unroll
            for (int l = 0; l < 8; l++) {
                int idx = tid + l * 256;
                int m   = idx >> 5;
                int d4  = (idx & 31) << 2;
                *(float4*)&KVs[m * QPAD + d4] =
                    *(const float4*)&vbase[(size_t)m * ROWSTRIDE + d4];
            }
        }
        __syncthreads();

        #pragma unroll 4
        for (int n = 0; n < 64; n++) {
            float4 v0 = *(const float4*)&KVs[n * QPAD + 4 * tx];
            float4 v1 = *(const float4*)&KVs[n * QPAD + 64 + 4 * tx];
            #pragma unroll
            for (int i = 0; i < 4; i++) {
                float p = Ps[(ty + 16 * i) * PPAD + n];
                o[i][0] = fmaf(p, v0.x, o[i][0]);
                o[i][1] = fmaf(p, v0.y, o[i][1]);
                o[i][2] = fmaf(p, v0.z, o[i][2]);
                o[i][3] = fmaf(p, v0.w, o[i][3]);
                o[i][4] = fmaf(p, v1.x, o[i][4]);
                o[i][5] = fmaf(p, v1.y, o[i][5]);
                o[i][6] = fmaf(p, v1.z, o[i][6]);
                o[i][7] = fmaf(p, v1.w, o[i][7]);
            }
        }
    }

    #pragma unroll
    for (int i = 0; i < 4; i++) {
        float inv = 1.0f / l_cur[i];
        size_t row = (size_t)(b * S_ + q0 + ty + 16 * i) * D_ + h * HD_;
        float4 w0, w1;
        w0.x = o[i][0] * inv; w0.y = o[i][1] * inv;
        w0.z = o[i][2] * inv; w0.w = o[i][3] * inv;
        w1.x = o[i][4] * inv; w1.y = o[i][5] * inv;
        w1.z = o[i][6] * inv; w1.w = o[i][7] * inv;
        *(float4*)&out[row + 4 * tx]      = w0;
        *(float4*)&out[row + 64 + 4 * tx] = w1;
    }
}

// ---------------------------------------------------------------------------
// kernel_launch
// ---------------------------------------------------------------------------
extern "C" void kernel_launch(void* const* d_in, const int* in_sizes, int n_in,
                              void* d_out, int out_size)
{
    const float* x     = (const float*)d_in[0];
    const float* alibi = (const float*)d_in[1];
    const float* pad   = (const float*)d_in[2];
    const float* Wqkv  = (const float*)d_in[3];
    const float* Aqkv  = (const float*)d_in[4];
    const float* Bqkv  = (const float*)d_in[5];
    const float* Wout  = (const float*)d_in[6];
    const float* Aout  = (const float*)d_in[7];
    const float* Bout  = (const float*)d_in[8];
    float* out = (float*)d_out;

    float *qkv_p, *attn_p;
    __nv_bfloat16 *xh, *xl, *wqh, *wql, *woh, *wol, *ah, *al;
    __nv_bfloat16 *bqt, *bot, *t1h, *t2h;
    cudaGetSymbolAddress((void**)&qkv_p,  g_qkv);
    cudaGetSymbolAddress((void**)&attn_p, g_attn);
    cudaGetSymbolAddress((void**)&xh,  g_xh);
    cudaGetSymbolAddress((void**)&xl,  g_xl);
    cudaGetSymbolAddress((void**)&wqh, g_wqh);
    cudaGetSymbolAddress((void**)&wql, g_wql);
    cudaGetSymbolAddress((void**)&woh, g_woh);
    cudaGetSymbolAddress((void**)&wol, g_wol);
    cudaGetSymbolAddress((void**)&ah,  g_ah);
    cudaGetSymbolAddress((void**)&al,  g_al);
    cudaGetSymbolAddress((void**)&bqt, g_bqt);
    cudaGetSymbolAddress((void**)&bot, g_bot);
    cudaGetSymbolAddress((void**)&t1h, g_t1h);
    cudaGetSymbolAddress((void**)&t2h, g_t2h);

    cudaFuncSetAttribute(attn_kernel,
                         cudaFuncAttributeMaxDynamicSharedMemorySize,
                         ATTN_SMEM_BYTES);
    cudaFuncSetAttribute(tc_gemm_bf16,
                         cudaFuncAttributeMaxDynamicSharedMemorySize,
                         TCG_SMEM);

    // pre-pass splits
    split_kernel<<<(M_TOK * D_ / 4 + 255) / 256, 256>>>(
        (const float4*)x, (uint2*)xh, (uint2*)xl, M_TOK * D_ / 4);
    split_kernel<<<(3 * D_ * D_ / 4 + 255) / 256, 256>>>(
        (const float4*)Wqkv, (uint2*)wqh, (uint2*)wql, 3 * D_ * D_ / 4);
    split_kernel<<<(D_ * D_ / 4 + 255) / 256, 256>>>(
        (const float4*)Wout, (uint2*)woh, (uint2*)wol, D_ * D_ / 4);
    transpose_scale_kernel<<<(3 * D_ * R_ + 255) / 256, 256>>>(
        Bqkv, bqt, 3 * D_, LORA_SCALE);
    transpose_scale_kernel<<<(D_ * R_ + 255) / 256, 256>>>(
        Bout, bot, D_, LORA_SCALE);

    // t1 = x @ Aqkv  (bf16 out)
    lora_down_kernel<<<M_TOK / 32, 256>>>(x, Aqkv, t1h, M_TOK, D_);

    // qkv = x @ Wqkv^T + lora   (bf16x3 tensor-core)
    {
        dim3 grid((3 * D_) / 128, M_TOK / 128);
        tc_gemm_bf16<<<grid, 256, TCG_SMEM>>>(xh, xl, wqh, wql, t1h, bqt,
                                              qkv_p, M_TOK, 3 * D_, D_);
    }

    // attention (fp32)
    {
        dim3 grid(S_ / 64, H_, B_);
        attn_kernel<<<grid, 256, ATTN_SMEM_BYTES>>>(qkv_p, alibi, pad, attn_p);
    }

    // split attention output
    split_kernel<<<(M_TOK * D_ / 4 + 255) / 256, 256>>>(
        (const float4*)attn_p, (uint2*)ah, (uint2*)al, M_TOK * D_ / 4);

    // t2 = attn @ Aout
    lora_down_kernel<<<M_TOK / 32, 256>>>(attn_p, Aout, t2h, M_TOK, D_);

    // out = attn @ Wout^T + lora   (bf16x3 tensor-core)
    {
        dim3 grid(D_ / 128, M_TOK / 128);
        tc_gemm_bf16<<<grid, 256, TCG_SMEM>>>(ah, al, woh, wol, t2h, bot,
                                              out, M_TOK, D_, D_);
    }
}

// round 5
// speedup vs baseline: 2.1070x; 1.4445x over previous
#include <cuda_runtime.h>
#include <cuda_bf16.h>
#include <cstdint>

// Problem constants
#define B_   2
#define S_   2048
#define D_   2048
#define H_   16
#define HD_  128
#define R_   32
#define M_TOK (B_ * S_)              // 4096 tokens
#define LORA_SCALE (1.0f / 32.0f)

// ---------------------------------------------------------------------------
// Scratch (allocation-free rule: __device__ globals)
// ---------------------------------------------------------------------------
static __device__ float g_attn[M_TOK * D_];      // fp32 attention output

static __device__ __align__(16) __nv_bfloat16 g_qkvh[M_TOK * 3 * D_];
static __device__ __align__(16) __nv_bfloat16 g_qkvl[M_TOK * 3 * D_];
static __device__ __align__(16) __nv_bfloat16 g_xh[M_TOK * D_];
static __device__ __align__(16) __nv_bfloat16 g_xl[M_TOK * D_];
static __device__ __align__(16) __nv_bfloat16 g_wqh[3 * D_ * D_];
static __device__ __align__(16) __nv_bfloat16 g_wql[3 * D_ * D_];
static __device__ __align__(16) __nv_bfloat16 g_woh[D_ * D_];
static __device__ __align__(16) __nv_bfloat16 g_wol[D_ * D_];
static __device__ __align__(16) __nv_bfloat16 g_ah[M_TOK * D_];
static __device__ __align__(16) __nv_bfloat16 g_al[M_TOK * D_];
static __device__ __align__(16) __nv_bfloat16 g_bqt[3 * D_ * R_];   // [6144][32]
static __device__ __align__(16) __nv_bfloat16 g_bot[D_ * R_];       // [2048][32]
static __device__ __align__(16) __nv_bfloat16 g_t1h[M_TOK * R_];
static __device__ __align__(16) __nv_bfloat16 g_t2h[M_TOK * R_];

// ---------------------------------------------------------------------------
// helpers
// ---------------------------------------------------------------------------
__device__ __forceinline__ uint32_t smem_u32(const void* p) {
    uint32_t a;
    asm("{ .reg .u64 t; cvta.to.shared.u64 t, %1; cvt.u32.u64 %0, t; }"
        : "=r"(a) : "l"(p));
    return a;
}
__device__ __forceinline__ void cp16(uint32_t dst, const void* src) {
    asm volatile("cp.async.cg.shared.global [%0], [%1], 16;"
                 :: "r"(dst), "l"(src) : "memory");
}
__device__ __forceinline__ void cp_commit() {
    asm volatile("cp.async.commit_group;" ::: "memory");
}
__device__ __forceinline__ void cp_wait1() {
    asm volatile("cp.async.wait_group 1;" ::: "memory");
}
__device__ __forceinline__ void ldm4(uint32_t& r0, uint32_t& r1,
                                     uint32_t& r2, uint32_t& r3, uint32_t addr) {
    asm volatile("ldmatrix.sync.aligned.m8n8.x4.shared.b16 {%0,%1,%2,%3}, [%4];"
                 : "=r"(r0), "=r"(r1), "=r"(r2), "=r"(r3) : "r"(addr));
}
__device__ __forceinline__ void ldm4t(uint32_t& r0, uint32_t& r1,
                                      uint32_t& r2, uint32_t& r3, uint32_t addr) {
    asm volatile("ldmatrix.sync.aligned.m8n8.x4.trans.shared.b16 {%0,%1,%2,%3}, [%4];"
                 : "=r"(r0), "=r"(r1), "=r"(r2), "=r"(r3) : "r"(addr));
}
__device__ __forceinline__ void mma16(float* c, const uint32_t* a, const uint32_t* b) {
    asm volatile(
        "mma.sync.aligned.m16n8k16.row.col.f32.bf16.bf16.f32 "
        "{%0,%1,%2,%3}, {%4,%5,%6,%7}, {%8,%9}, {%0,%1,%2,%3};"
        : "+f"(c[0]), "+f"(c[1]), "+f"(c[2]), "+f"(c[3])
        : "r"(a[0]), "r"(a[1]), "r"(a[2]), "r"(a[3]), "r"(b[0]), "r"(b[1]));
}
// pack two fp32 -> bf16x2: hi by truncation
__device__ __forceinline__ uint32_t pack_hi(float x, float y) {
    return (__float_as_uint(y) & 0xffff0000u) | (__float_as_uint(x) >> 16);
}
// residuals (x - trunc_bf16(x)) packed RN
__device__ __forceinline__ uint32_t pack_lo(float x, float y) {
    float lx = x - __uint_as_float(__float_as_uint(x) & 0xffff0000u);
    float ly = y - __uint_as_float(__float_as_uint(y) & 0xffff0000u);
    __nv_bfloat162 t = __floats2bfloat162_rn(lx, ly);
    return *(uint32_t*)&t;
}

// ---------------------------------------------------------------------------
// Pre-pass: split fp32 -> bf16 hi (truncation) + bf16 lo (RN residual)
// ---------------------------------------------------------------------------
__global__ void __launch_bounds__(256) split_kernel(
    const float4* __restrict__ src, uint2* __restrict__ hi,
    uint2* __restrict__ lo, int n4)
{
    int i = blockIdx.x * 256 + threadIdx.x;
    if (i >= n4) return;
    float4 v = src[i];
    uint2 h, l;
    h.x = pack_hi(v.x, v.y);
    h.y = pack_hi(v.z, v.w);
    l.x = pack_lo(v.x, v.y);
    l.y = pack_lo(v.z, v.w);
    hi[i] = h;
    lo[i] = l;
}

// Pre-pass: Bq[32,N] -> out[N][32] bf16(RN), scaled
__global__ void __launch_bounds__(256) transpose_scale_kernel(
    const float* __restrict__ Bq, __nv_bfloat16* __restrict__ out,
    int N, float scale)
{
    int idx = blockIdx.x * 256 + threadIdx.x;
    int k = idx & 31;
    int n = idx >> 5;
    if (n < N)
        out[(size_t)n * 32 + k] = __float2bfloat16(Bq[(size_t)k * N + n] * scale);
}

// ---------------------------------------------------------------------------
// Pure-bf16 fused GEMM (bf16x3 via pre-split operands):
//   C = (Ah+Al) @ (Bh+Bl)^T + T @ Bqt^T
// Output: fp32 Cf, or split bf16 (Chi, Clo) when Cf == nullptr.
// ---------------------------------------------------------------------------
#define OFF_AH 0
#define OFF_AL 6144
#define OFF_BH 12288
#define OFF_BL 18432
#define STAGE_B 24576
#define TCG_SMEM (3 * STAGE_B)      // 73728 bytes

__global__ void __launch_bounds__(256, 2) tc_gemm_bf16(
    const __nv_bfloat16* __restrict__ Ah, const __nv_bfloat16* __restrict__ Al,
    const __nv_bfloat16* __restrict__ Bh, const __nv_bfloat16* __restrict__ Bl,
    const __nv_bfloat16* __restrict__ Tm, const __nv_bfloat16* __restrict__ Bqt,
    float* __restrict__ Cf, __nv_bfloat16* __restrict__ Chi,
    __nv_bfloat16* __restrict__ Clo, int M, int N, int K)
{
    extern __shared__ __align__(128) char smem[];
    const uint32_t sbase = smem_u32(smem);

    const int tid  = threadIdx.x;
    const int wid  = tid >> 5;
    const int lane = tid & 31;
    const int g    = lane >> 2;
    const int q    = lane & 3;
    const int warpM = (wid & 1) * 64;
    const int warpN = (wid >> 1) * 32;

    const int n0 = blockIdx.x * 128;
    const int m0 = blockIdx.y * 128;

    const int kc    = K >> 4;
    const int total = kc + 2;

    float acc[4][4][4];
    #pragma unroll
    for (int i = 0; i < 4; i++)
        #pragma unroll
        for (int j = 0; j < 4; j++)
            #pragma unroll
            for (int e = 0; e < 4; e++) acc[i][j][e] = 0.f;

    const int pr = tid >> 1;
    const int ps = tid & 1;
    auto issue = [&](int c, int s) {
        const uint32_t st = sbase + (uint32_t)s * STAGE_B;
        const uint32_t doff = (uint32_t)pr * 48u + (uint32_t)ps * 16u;
        if (c < kc) {
            size_t ao = (size_t)(m0 + pr) * K + c * 16 + ps * 8;
            size_t bo = (size_t)(n0 + pr) * K + c * 16 + ps * 8;
            cp16(st + OFF_AH + doff, Ah + ao);
            cp16(st + OFF_AL + doff, Al + ao);
            cp16(st + OFF_BH + doff, Bh + bo);
            cp16(st + OFF_BL + doff, Bl + bo);
        } else {
            int kl = (c - kc) * 16 + ps * 8;
            cp16(st + OFF_AH + doff, Tm  + (size_t)(m0 + pr) * 32 + kl);
            cp16(st + OFF_BH + doff, Bqt + (size_t)(n0 + pr) * 32 + kl);
        }
        cp_commit();
    };

    issue(0, 0);
    issue(1, 1);

    const int mi = lane >> 3;
    const int l7 = lane & 7;

    for (int i = 0; i < total; i++) {
        cp_wait1();
        __syncthreads();
        if (i + 2 < total) issue(i + 2, (i + 2) % 3);
        else cp_commit();

        const uint32_t st = sbase + (uint32_t)(i % 3) * STAGE_B;
        const bool lora = (i >= kc);

        uint32_t bh[4][2], bl[4][2];
        #pragma unroll
        for (int bg = 0; bg < 2; bg++) {
            uint32_t rowB = warpN + bg * 16 + ((mi >> 1) << 3) + l7;
            uint32_t addr = st + OFF_BH + rowB * 48u + (uint32_t)(mi & 1) * 16u;
            ldm4(bh[2 * bg][0], bh[2 * bg][1], bh[2 * bg + 1][0], bh[2 * bg + 1][1], addr);
            if (!lora)
                ldm4(bl[2 * bg][0], bl[2 * bg][1], bl[2 * bg + 1][0], bl[2 * bg + 1][1],
                     addr + (OFF_BL - OFF_BH));
        }
        #pragma unroll
        for (int mt = 0; mt < 4; mt++) {
            uint32_t rowA = warpM + mt * 16 + ((mi & 1) << 3) + l7;
            uint32_t addrA = st + OFF_AH + rowA * 48u + (uint32_t)(mi >> 1) * 16u;
            uint32_t ah[4], al[4];
            ldm4(ah[0], ah[1], ah[2], ah[3], addrA);
            if (!lora)
                ldm4(al[0], al[1], al[2], al[3], addrA + (OFF_AL - OFF_AH));
            #pragma unroll
            for (int nt = 0; nt < 4; nt++) {
                mma16(acc[mt][nt], ah, bh[nt]);
                if (!lora) {
                    mma16(acc[mt][nt], al, bh[nt]);
                    mma16(acc[mt][nt], ah, bl[nt]);
                }
            }
        }
    }

    // epilogue
    #pragma unroll
    for (int mt = 0; mt < 4; mt++) {
        int row = m0 + warpM + mt * 16 + g;
        #pragma unroll
        for (int nt = 0; nt < 4; nt++) {
            int col = n0 + warpN + nt * 8 + 2 * q;
            if (Cf) {
                *(float2*)&Cf[(size_t)row * N + col] =
                    make_float2(acc[mt][nt][0], acc[mt][nt][1]);
                *(float2*)&Cf[(size_t)(row + 8) * N + col] =
                    make_float2(acc[mt][nt][2], acc[mt][nt][3]);
            } else {
                size_t i0 = (size_t)row * N + col;
                size_t i1 = (size_t)(row + 8) * N + col;
                *(uint32_t*)&Chi[i0] = pack_hi(acc[mt][nt][0], acc[mt][nt][1]);
                *(uint32_t*)&Clo[i0] = pack_lo(acc[mt][nt][0], acc[mt][nt][1]);
                *(uint32_t*)&Chi[i1] = pack_hi(acc[mt][nt][2], acc[mt][nt][3]);
                *(uint32_t*)&Clo[i1] = pack_lo(acc[mt][nt][2], acc[mt][nt][3]);
            }
        }
    }
}

// ---------------------------------------------------------------------------
// Small LoRA-down GEMM: T[M,32] = X[M,K] @ A[K,32]   (writes bf16 RN)
// ---------------------------------------------------------------------------
__global__ void __launch_bounds__(256) lora_down_kernel(
    const float* __restrict__ X, const float* __restrict__ Amat,
    __nv_bfloat16* __restrict__ Tout, int M, int K)
{
    __shared__ __align__(16) float Xs[32][68];
    __shared__ __align__(16) float As2[64][36];

    const int tid = threadIdx.x;
    const int m0  = blockIdx.x * 32;
    const int n   = tid & 31;
    const int mq  = (tid >> 5) * 4;

    float acc[4] = {0.f, 0.f, 0.f, 0.f};

    for (int k0 = 0; k0 < K; k0 += 64) {
        __syncthreads();
        #pragma unroll
        for (int l = 0; l < 2; l++) {
            int idx = tid + l * 256;
            int m   = idx >> 4;
            int k4  = (idx & 15) << 2;
            *(float4*)&Xs[m][k4] =
                *(const float4*)&X[(size_t)(m0 + m) * K + k0 + k4];
        }
        #pragma unroll
        for (int l = 0; l < 2; l++) {
            int idx = tid + l * 256;
            int kk  = idx >> 3;
            int n4  = (idx & 7) << 2;
            *(float4*)&As2[kk][n4] =
                *(const float4*)&Amat[(size_t)(k0 + kk) * 32 + n4];
        }
        __syncthreads();
        #pragma unroll 16
        for (int kk = 0; kk < 64; kk++) {
            float a = As2[kk][n];
            acc[0] = fmaf(Xs[mq + 0][kk], a, acc[0]);
            acc[1] = fmaf(Xs[mq + 1][kk], a, acc[1]);
            acc[2] = fmaf(Xs[mq + 2][kk], a, acc[2]);
            acc[3] = fmaf(Xs[mq + 3][kk], a, acc[3]);
        }
    }
    #pragma unroll
    for (int i = 0; i < 4; i++)
        Tout[(size_t)(m0 + mq + i) * 32 + n] = __float2bfloat16(acc[i]);
}

// ---------------------------------------------------------------------------
// Tensor-core flash attention (bf16x3 hi/lo, online softmax).
// CTA: 256 threads, 8 warps, 128 q-rows.  Grid: (S/128, H, B).
// smem: Qh/Ql [128][136]bf16; 2-stage KV: Kh/Kl/Vh/Vl [64][136]bf16.
// rows padded to 272B -> conflict-free ldmatrix.
// ---------------------------------------------------------------------------
#define AROWB 272
#define QH_OFF 0
#define QL_OFF (128 * AROWB)
#define KV_OFF (2 * 128 * AROWB)
#define KHO 0
#define KLO (64 * AROWB)
#define VHO (2 * 64 * AROWB)
#define VLO (3 * 64 * AROWB)
#define ST_B (4 * 64 * AROWB)
#define ATTN_SMEM (KV_OFF + 2 * ST_B)    // 208896

__global__ void __launch_bounds__(256, 1) attn_mma(
    const __nv_bfloat16* __restrict__ qkvh, const __nv_bfloat16* __restrict__ qkvl,
    const float* __restrict__ alibi, const float* __restrict__ pad,
    float* __restrict__ outf, __nv_bfloat16* __restrict__ outh,
    __nv_bfloat16* __restrict__ outl)
{
    extern __shared__ __align__(128) char smem[];
    const uint32_t sb = smem_u32(smem);
    const int tid = threadIdx.x, wid = tid >> 5, lane = tid & 31;
    const int g = lane >> 2, q = lane & 3, l7 = lane & 7;
    const int q0 = blockIdx.x * 128, h = blockIdx.y, b = blockIdx.z;

    const size_t tokbase = (size_t)(b * S_);

    // --- load Q (both hi/lo) + KV tile 0 as group 0 ---
    {
        const __nv_bfloat16* bH = qkvh + (tokbase + q0) * 6144 + h * 128;
        const __nv_bfloat16* bL = qkvl + (tokbase + q0) * 6144 + h * 128;
        #pragma unroll
        for (int j = 0; j < 8; j++) {
            int idx = tid + j * 256;
            int row = idx >> 4, seg = idx & 15;
            uint32_t off = (uint32_t)row * AROWB + seg * 16;
            cp16(sb + QH_OFF + off, bH + (size_t)row * 6144 + seg * 8);
            cp16(sb + QL_OFF + off, bL + (size_t)row * 6144 + seg * 8);
        }
    }
    auto loadKV = [&](int kt, int st) {
        const uint32_t base = sb + KV_OFF + (uint32_t)st * ST_B;
        const __nv_bfloat16* kH = qkvh + (tokbase + kt * 64) * 6144 + D_ + h * 128;
        const __nv_bfloat16* kL = qkvl + (tokbase + kt * 64) * 6144 + D_ + h * 128;
        const __nv_bfloat16* vH = kH + D_;
        const __nv_bfloat16* vL = kL + D_;
        #pragma unroll
        for (int j = 0; j < 4; j++) {
            int idx = tid + j * 256;
            int row = idx >> 4, seg = idx & 15;
            uint32_t off = (uint32_t)row * AROWB + seg * 16;
            size_t go = (size_t)row * 6144 + seg * 8;
            cp16(base + KHO + off, kH + go);
            cp16(base + KLO + off, kL + go);
            cp16(base + VHO + off, vH + go);
            cp16(base + VLO + off, vL + go);
        }
    };
    loadKV(0, 0); cp_commit();
    loadKV(1, 1); cp_commit();

    float o[16][4];
    #pragma unroll
    for (int i = 0; i < 16; i++)
        #pragma unroll
        for (int e = 0; e < 4; e++) o[i][e] = 0.f;
    float m0r = -1e30f, m1r = -1e30f, l0r = 0.f, l1r = 0.f;

    const float sscale = 0.08838834764831845f;   // 1/sqrt(128)

    // fragment address components
    const uint32_t qoff = (uint32_t)(wid * 16 + ((lane >> 3) & 1) * 8 + l7) * AROWB
                        + ((lane >> 4) & 1) * 16;
    const uint32_t koff = (uint32_t)(((lane >> 4) & 1) * 8 + l7) * AROWB
                        + ((lane >> 3) & 1) * 16;
    const uint32_t voff = (uint32_t)(((lane >> 3) & 1) * 8 + l7) * AROWB
                        + ((lane >> 4) & 1) * 16;

    const float* arow0 = alibi + ((size_t)h * S_ + (q0 + wid * 16 + g)) * S_;
    const float* arow1 = arow0 + 8 * S_;
    const float* prow  = pad + (size_t)b * S_;

    for (int kt = 0; kt < S_ / 64; kt++) {
        cp_wait1();
        __syncthreads();
        const uint32_t st = sb + KV_OFF + (uint32_t)(kt & 1) * ST_B;
        const int k0 = kt * 64;

        // ---- QK^T (bf16x3) ----
        float c[8][4];
        #pragma unroll
        for (int i = 0; i < 8; i++)
            #pragma unroll
            for (int e = 0; e < 4; e++) c[i][e] = 0.f;

        #pragma unroll
        for (int kc = 0; kc < 8; kc++) {
            uint32_t qh4[4], ql4[4];
            ldm4(qh4[0], qh4[1], qh4[2], qh4[3], sb + QH_OFF + qoff + kc * 32);
            ldm4(ql4[0], ql4[1], ql4[2], ql4[3], sb + QL_OFF + qoff + kc * 32);
            #pragma unroll
            for (int np = 0; np < 4; np++) {
                uint32_t kh[4], kl[4];
                uint32_t ka = st + KHO + koff + (uint32_t)np * (16 * AROWB) + kc * 32;
                ldm4(kh[0], kh[1], kh[2], kh[3], ka);
                ldm4(kl[0], kl[1], kl[2], kl[3], ka + (KLO - KHO));
                mma16(c[2 * np],     qh4, &kh[0]);
                mma16(c[2 * np + 1], qh4, &kh[2]);
                mma16(c[2 * np],     ql4, &kh[0]);
                mma16(c[2 * np + 1], ql4, &kh[2]);
                mma16(c[2 * np],     qh4, &kl[0]);
                mma16(c[2 * np + 1], qh4, &kl[2]);
            }
        }

        // ---- bias + online softmax ----
        #pragma unroll
        for (int nt = 0; nt < 8; nt++) {
            int col = k0 + nt * 8 + 2 * q;
            float2 a0 = *(const float2*)(arow0 + col);
            float2 a1 = *(const float2*)(arow1 + col);
            float2 pd = *(const float2*)(prow + col);
            c[nt][0] = fmaf(c[nt][0], sscale, a0.x + pd.x);
            c[nt][1] = fmaf(c[nt][1], sscale, a0.y + pd.y);
            c[nt][2] = fmaf(c[nt][2], sscale, a1.x + pd.x);
            c[nt][3] = fmaf(c[nt][3], sscale, a1.y + pd.y);
        }
        float mx0 = -1e30f, mx1 = -1e30f;
        #pragma unroll
        for (int nt = 0; nt < 8; nt++) {
            mx0 = fmaxf(mx0, fmaxf(c[nt][0], c[nt][1]));
            mx1 = fmaxf(mx1, fmaxf(c[nt][2], c[nt][3]));
        }
        mx0 = fmaxf(mx0, __shfl_xor_sync(0xffffffffu, mx0, 1));
        mx0 = fmaxf(mx0, __shfl_xor_sync(0xffffffffu, mx0, 2));
        mx1 = fmaxf(mx1, __shfl_xor_sync(0xffffffffu, mx1, 1));
        mx1 = fmaxf(mx1, __shfl_xor_sync(0xffffffffu, mx1, 2));
        float mn0 = fmaxf(m0r, mx0), mn1 = fmaxf(m1r, mx1);
        float cr0 = __expf(m0r - mn0), cr1 = __expf(m1r - mn1);
        m0r = mn0; m1r = mn1;
        float s0 = 0.f, s1 = 0.f;
        #pragma unroll
        for (int nt = 0; nt < 8; nt++) {
            c[nt][0] = __expf(c[nt][0] - mn0);
            c[nt][1] = __expf(c[nt][1] - mn0);
            c[nt][2] = __expf(c[nt][2] - mn1);
            c[nt][3] = __expf(c[nt][3] - mn1);
            s0 += c[nt][0] + c[nt][1];
            s1 += c[nt][2] + c[nt][3];
        }
        s0 += __shfl_xor_sync(0xffffffffu, s0, 1);
        s0 += __shfl_xor_sync(0xffffffffu, s0, 2);
        s1 += __shfl_xor_sync(0xffffffffu, s1, 1);
        s1 += __shfl_xor_sync(0xffffffffu, s1, 2);
        l0r = l0r * cr0 + s0;
        l1r = l1r * cr1 + s1;
        #pragma unroll
        for (int i = 0; i < 16; i++) {
            o[i][0] *= cr0; o[i][1] *= cr0;
            o[i][2] *= cr1; o[i][3] *= cr1;
        }

        // ---- PV (bf16x3; P split in registers) ----
        #pragma unroll
        for (int kc = 0; kc < 4; kc++) {
            uint32_t ph[4], pl[4];
            ph[0] = pack_hi(c[2 * kc][0],     c[2 * kc][1]);
            ph[1] = pack_hi(c[2 * kc][2],     c[2 * kc][3]);
            ph[2] = pack_hi(c[2 * kc + 1][0], c[2 * kc + 1][1]);
            ph[3] = pack_hi(c[2 * kc + 1][2], c[2 * kc + 1][3]);
            pl[0] = pack_lo(c[2 * kc][0],     c[2 * kc][1]);
            pl[1] = pack_lo(c[2 * kc][2],     c[2 * kc][3]);
            pl[2] = pack_lo(c[2 * kc + 1][0], c[2 * kc + 1][1]);
            pl[3] = pack_lo(c[2 * kc + 1][2], c[2 * kc + 1][3]);
            uint32_t vrow = st + VHO + voff + (uint32_t)kc * (16 * AROWB);
            #pragma unroll
            for (int dg = 0; dg < 8; dg++) {
                uint32_t vh[4], vl[4];
                ldm4t(vh[0], vh[1], vh[2], vh[3], vrow + dg * 32);
                ldm4t(vl[0], vl[1], vl[2], vl[3], vrow + dg * 32 + (VLO - VHO));
                mma16(o[2 * dg],     ph, &vh[0]);
                mma16(o[2 * dg + 1], ph, &vh[2]);
                mma16(o[2 * dg],     pl, &vh[0]);
                mma16(o[2 * dg + 1], pl, &vh[2]);
                mma16(o[2 * dg],     ph, &vl[0]);
                mma16(o[2 * dg + 1], ph, &vl[2]);
            }
        }

        __syncthreads();
        if (kt + 2 < S_ / 64) { loadKV(kt + 2, kt & 1); cp_commit(); }
        else cp_commit();
    }

    // ---- epilogue ----
    float inv0 = 1.0f / l0r, inv1 = 1.0f / l1r;
    size_t row0 = tokbase + q0 + wid * 16 + g;
    size_t row1 = row0 + 8;
    #pragma unroll
    for (int nt = 0; nt < 16; nt++) {
        int col = h * 128 + nt * 8 + 2 * q;
        float f0 = o[nt][0] * inv0, f1 = o[nt][1] * inv0;
        float f2 = o[nt][2] * inv1, f3 = o[nt][3] * inv1;
        *(float2*)&outf[row0 * D_ + col] = make_float2(f0, f1);
        *(float2*)&outf[row1 * D_ + col] = make_float2(f2, f3);
        *(uint32_t*)&outh[row0 * D_ + col] = pack_hi(f0, f1);
        *(uint32_t*)&outl[row0 * D_ + col] = pack_lo(f0, f1);
        *(uint32_t*)&outh[row1 * D_ + col] = pack_hi(f2, f3);
        *(uint32_t*)&outl[row1 * D_ + col] = pack_lo(f2, f3);
    }
}

// ---------------------------------------------------------------------------
// kernel_launch
// ---------------------------------------------------------------------------
extern "C" void kernel_launch(void* const* d_in, const int* in_sizes, int n_in,
                              void* d_out, int out_size)
{
    const float* x     = (const float*)d_in[0];
    const float* alibi = (const float*)d_in[1];
    const float* pad   = (const float*)d_in[2];
    const float* Wqkv  = (const float*)d_in[3];
    const float* Aqkv  = (const float*)d_in[4];
    const float* Bqkv  = (const float*)d_in[5];
    const float* Wout  = (const float*)d_in[6];
    const float* Aout  = (const float*)d_in[7];
    const float* Bout  = (const float*)d_in[8];
    float* out = (float*)d_out;

    float *attn_p;
    __nv_bfloat16 *qkvh, *qkvl, *xh, *xl, *wqh, *wql, *woh, *wol, *ah, *al;
    __nv_bfloat16 *bqt, *bot, *t1h, *t2h;
    cudaGetSymbolAddress((void**)&attn_p, g_attn);
    cudaGetSymbolAddress((void**)&qkvh, g_qkvh);
    cudaGetSymbolAddress((void**)&qkvl, g_qkvl);
    cudaGetSymbolAddress((void**)&xh,  g_xh);
    cudaGetSymbolAddress((void**)&xl,  g_xl);
    cudaGetSymbolAddress((void**)&wqh, g_wqh);
    cudaGetSymbolAddress((void**)&wql, g_wql);
    cudaGetSymbolAddress((void**)&woh, g_woh);
    cudaGetSymbolAddress((void**)&wol, g_wol);
    cudaGetSymbolAddress((void**)&ah,  g_ah);
    cudaGetSymbolAddress((void**)&al,  g_al);
    cudaGetSymbolAddress((void**)&bqt, g_bqt);
    cudaGetSymbolAddress((void**)&bot, g_bot);
    cudaGetSymbolAddress((void**)&t1h, g_t1h);
    cudaGetSymbolAddress((void**)&t2h, g_t2h);

    cudaFuncSetAttribute(tc_gemm_bf16,
                         cudaFuncAttributeMaxDynamicSharedMemorySize, TCG_SMEM);
    cudaFuncSetAttribute(attn_mma,
                         cudaFuncAttributeMaxDynamicSharedMemorySize, ATTN_SMEM);

    // pre-pass splits
    split_kernel<<<(M_TOK * D_ / 4 + 255) / 256, 256>>>(
        (const float4*)x, (uint2*)xh, (uint2*)xl, M_TOK * D_ / 4);
    split_kernel<<<(3 * D_ * D_ / 4 + 255) / 256, 256>>>(
        (const float4*)Wqkv, (uint2*)wqh, (uint2*)wql, 3 * D_ * D_ / 4);
    split_kernel<<<(D_ * D_ / 4 + 255) / 256, 256>>>(
        (const float4*)Wout, (uint2*)woh, (uint2*)wol, D_ * D_ / 4);
    transpose_scale_kernel<<<(3 * D_ * R_ + 255) / 256, 256>>>(
        Bqkv, bqt, 3 * D_, LORA_SCALE);
    transpose_scale_kernel<<<(D_ * R_ + 255) / 256, 256>>>(
        Bout, bot, D_, LORA_SCALE);

    // t1 = x @ Aqkv
    lora_down_kernel<<<M_TOK / 32, 256>>>(x, Aqkv, t1h, M_TOK, D_);

    // qkv = x @ Wqkv^T + lora  -> bf16 hi/lo directly
    {
        dim3 grid((3 * D_) / 128, M_TOK / 128);
        tc_gemm_bf16<<<grid, 256, TCG_SMEM>>>(xh, xl, wqh, wql, t1h, bqt,
                                              nullptr, qkvh, qkvl,
                                              M_TOK, 3 * D_, D_);
    }

    // attention (tensor-core, bf16x3)
    {
        dim3 grid(S_ / 128, H_, B_);
        attn_mma<<<grid, 256, ATTN_SMEM>>>(qkvh, qkvl, alibi, pad,
                                           attn_p, ah, al);
    }

    // t2 = attn @ Aout
    lora_down_kernel<<<M_TOK / 32, 256>>>(attn_p, Aout, t2h, M_TOK, D_);

    // out = attn @ Wout^T + lora  -> fp32
    {
        dim3 grid(D_ / 128, M_TOK / 128);
        tc_gemm_bf16<<<grid, 256, TCG_SMEM>>>(ah, al, woh, wol, t2h, bot,
                                              out, nullptr, nullptr,
                                              M_TOK, D_, D_);
    }
}